// round 8
// baseline (speedup 1.0000x reference)
#include <cuda_runtime.h>
#include <cuda_bf16.h>
#include <stdint.h>
#include <math.h>

#define NS 50000
#define NA 50000
#define EDG 1600000
#define NBIN 50000
#define SCAN_TILES 196          // 196*256 = 50176 >= NBIN
#define SCAN_BLOCKS (2 * SCAN_TILES)

// Scratch (device globals; no allocation allowed)
__device__ __align__(16) float g_Apre[NA * 32];
__device__ __align__(16) float g_Bpre[NS * 32];
__device__ __align__(16) float g_Cpre[NS * 32];
__device__ __align__(16) float g_Dpre[NS * 32];
__device__ __align__(16) float g_sum_u[NS * 64];
__device__ __align__(16) float g_sum_h[NS * 64];
// sort scratch
__device__ int  g_cnt [2 * NBIN];
__device__ int  g_rank[2 * NBIN];
__device__ int  g_off [2 * NBIN];
__device__ int  g_btot[SCAN_BLOCKS];
__device__ __align__(16) int2 g_rec [2 * EDG];   // {src, dis-bits} in sorted order
__device__ int  g_sdst[2 * EDG];                 // dst in sorted order

__device__ __forceinline__ float leaky(float x) { return fmaxf(x, 0.01f * x); }
__device__ __forceinline__ float tanh_fast(float x) {
    float r; asm("tanh.approx.f32 %0, %1;" : "=f"(r) : "f"(x)); return r;
}
__device__ __forceinline__ uint32_t smem_u32(const void* p) {
    uint32_t a;
    asm("{ .reg .u64 t; cvta.to.shared.u64 t, %1; cvt.u32.u64 %0, t; }"
        : "=r"(a) : "l"(p));
    return a;
}
__device__ __forceinline__ uint32_t pack_bf16x2(__nv_bfloat16 a, __nv_bfloat16 b) {
    uint16_t ua = *reinterpret_cast<uint16_t*>(&a);
    uint16_t ub = *reinterpret_cast<uint16_t*>(&b);
    return (uint32_t)ua | ((uint32_t)ub << 16);
}
__device__ __forceinline__ uint32_t cvt_bf16x2(float lo_elem, float hi_elem) {
    uint32_t r;
    asm("cvt.rn.bf16x2.f32 %0, %1, %2;" : "=r"(r) : "f"(hi_elem), "f"(lo_elem));
    return r;
}
__device__ __forceinline__ void ldsm_x4(uint32_t addr, uint32_t& a0, uint32_t& a1,
                                        uint32_t& a2, uint32_t& a3) {
    asm volatile("ldmatrix.sync.aligned.m8n8.x4.shared.b16 {%0,%1,%2,%3}, [%4];"
                 : "=r"(a0), "=r"(a1), "=r"(a2), "=r"(a3) : "r"(addr));
}
__device__ __forceinline__ void mma_bf16(float& c0, float& c1, float& c2, float& c3,
                                         uint32_t a0, uint32_t a1, uint32_t a2, uint32_t a3,
                                         uint32_t b0, uint32_t b1) {
    asm volatile(
        "mma.sync.aligned.m16n8k16.row.col.f32.bf16.bf16.f32 "
        "{%0,%1,%2,%3}, {%4,%5,%6,%7}, {%8,%9}, {%0,%1,%2,%3};"
        : "+f"(c0), "+f"(c1), "+f"(c2), "+f"(c3)
        : "r"(a0), "r"(a1), "r"(a2), "r"(a3), "r"(b0), "r"(b1));
}
__device__ __forceinline__ void red_v2(float* p, float a, float b) {
    asm volatile("red.global.add.v2.f32 [%0], {%1, %2};"
                 :: "l"(p), "f"(a), "f"(b) : "memory");
}

// ---------------------------------------------------------------------------
// Fused node-side precompute (unchanged)
// ---------------------------------------------------------------------------
__global__ void __launch_bounds__(256) pre_kernel(
    const float* __restrict__ pos_s,
    const float* __restrict__ pos_a,
    const float* __restrict__ u,
    const float* __restrict__ h,
    const float* __restrict__ a2s_W1, const float* __restrict__ a2s_b1,
    const float* __restrict__ s2s_W1, const float* __restrict__ s2s_b1)
{
    int lane = threadIdx.x & 31;
    int task = (blockIdx.x * blockDim.x + threadIdx.x) >> 5;

    if (task < NS) {
        int node = task;
        float p0 = __ldg(pos_s + 2 * node);
        float p1 = __ldg(pos_s + 2 * node + 1);
        g_Bpre[node * 32 + lane] =
            p0 * __ldg(a2s_W1 + 2 * 32 + lane) + p1 * __ldg(a2s_W1 + 3 * 32 + lane);
        g_Dpre[node * 32 + lane] =
            p0 * __ldg(s2s_W1 + 2 * 32 + lane) + p1 * __ldg(s2s_W1 + 3 * 32 + lane);
        g_sum_u[node * 64 + lane]      = 0.f;
        g_sum_u[node * 64 + 32 + lane] = 0.f;
        g_sum_h[node * 64 + lane]      = 0.f;
        g_sum_h[node * 64 + 32 + lane] = 0.f;
    } else if (task < NS + NA) {
        int node = task - NS;
        const float* W1 = a2s_W1;
        float p0 = __ldg(pos_a + 2 * node);
        float p1 = __ldg(pos_a + 2 * node + 1);
        float acc = __ldg(a2s_b1 + lane)
                  + p0 * __ldg(W1 + 0 * 32 + lane)
                  + p1 * __ldg(W1 + 1 * 32 + lane);
        const float4* u4 = reinterpret_cast<const float4*>(u) + node * 4;
#pragma unroll
        for (int q = 0; q < 4; ++q) {
            float4 v = __ldg(u4 + q);
            acc = fmaf(v.x, __ldg(W1 + (5 + 4 * q + 0) * 32 + lane), acc);
            acc = fmaf(v.y, __ldg(W1 + (5 + 4 * q + 1) * 32 + lane), acc);
            acc = fmaf(v.z, __ldg(W1 + (5 + 4 * q + 2) * 32 + lane), acc);
            acc = fmaf(v.w, __ldg(W1 + (5 + 4 * q + 3) * 32 + lane), acc);
        }
        g_Apre[node * 32 + lane] = acc;
    } else if (task < NS + NA + NS) {
        int node = task - NS - NA;
        const float* W1 = s2s_W1;
        float p0 = __ldg(pos_s + 2 * node);
        float p1 = __ldg(pos_s + 2 * node + 1);
        float acc = __ldg(s2s_b1 + lane)
                  + p0 * __ldg(W1 + 0 * 32 + lane)
                  + p1 * __ldg(W1 + 1 * 32 + lane);
        const float4* h4 = reinterpret_cast<const float4*>(h) + node * 16;
#pragma unroll
        for (int q = 0; q < 16; ++q) {
            float4 v = __ldg(h4 + q);
            acc = fmaf(v.x, __ldg(W1 + (5 + 4 * q + 0) * 32 + lane), acc);
            acc = fmaf(v.y, __ldg(W1 + (5 + 4 * q + 1) * 32 + lane), acc);
            acc = fmaf(v.z, __ldg(W1 + (5 + 4 * q + 2) * 32 + lane), acc);
            acc = fmaf(v.w, __ldg(W1 + (5 + 4 * q + 3) * 32 + lane), acc);
        }
        g_Cpre[node * 32 + lane] = acc;
    }
}

// ---------------------------------------------------------------------------
// Counting sort by dst (both graphs in one set of launches)
// ---------------------------------------------------------------------------
__global__ void __launch_bounds__(256) sort_zero() {
    int i = blockIdx.x * 256 + threadIdx.x;
    if (i < 2 * NBIN) g_cnt[i] = 0;
}

__global__ void __launch_bounds__(256) sort_hist(
    const int* __restrict__ d0, const int* __restrict__ d1)
{
    int t = blockIdx.x * 256 + threadIdx.x;
    if (t < EDG)            atomicAdd(&g_cnt[__ldg(d0 + t)], 1);
    else if (t < 2 * EDG)   atomicAdd(&g_cnt[NBIN + __ldg(d1 + t - EDG)], 1);
}

__global__ void __launch_bounds__(256) scan_blocks() {
    __shared__ int ss[256];
    int graph = blockIdx.x / SCAN_TILES;
    int tb    = blockIdx.x % SCAN_TILES;
    int tid   = threadIdx.x;
    int i     = tb * 256 + tid;
    int gi    = graph * NBIN + i;
    int v = (i < NBIN) ? g_cnt[gi] : 0;
    ss[tid] = v;
    __syncthreads();
#pragma unroll
    for (int o = 1; o < 256; o <<= 1) {
        int t = (tid >= o) ? ss[tid - o] : 0;
        __syncthreads();
        ss[tid] += t;
        __syncthreads();
    }
    if (i < NBIN) g_off[gi] = ss[tid] - v;   // exclusive within tile
    if (tid == 255) g_btot[blockIdx.x] = ss[tid];
}

__global__ void __launch_bounds__(512) scan_tops() {
    __shared__ int sb[SCAN_BLOCKS];
    int tid = threadIdx.x;
    if (tid < SCAN_BLOCKS) sb[tid] = g_btot[tid];
    __syncthreads();
    if (tid < 2) {
        int base = tid * SCAN_TILES;
        int acc = 0;
        for (int i = 0; i < SCAN_TILES; ++i) {
            int t = sb[base + i];
            sb[base + i] = acc;
            acc += t;
        }
    }
    __syncthreads();
    if (tid < SCAN_BLOCKS) g_btot[tid] = sb[tid];
}

__global__ void __launch_bounds__(256) scan_apply() {
    int graph = blockIdx.x / SCAN_TILES;
    int tb    = blockIdx.x % SCAN_TILES;
    int i     = tb * 256 + threadIdx.x;
    if (i < NBIN) {
        int gi = graph * NBIN + i;
        g_off[gi] += g_btot[blockIdx.x];
        g_rank[gi] = 0;
    }
}

__global__ void __launch_bounds__(256) sort_place(
    const int* __restrict__ s0, const int* __restrict__ d0, const float* __restrict__ x0,
    const int* __restrict__ s1, const int* __restrict__ d1, const float* __restrict__ x1)
{
    int t = blockIdx.x * 256 + threadIdx.x;
    if (t < EDG) {
        int d = __ldg(d0 + t);
        int pos = g_off[d] + atomicAdd(&g_rank[d], 1);
        g_rec[pos]  = make_int2(__ldg(s0 + t), __float_as_int(__ldg(x0 + t)));
        g_sdst[pos] = d;
    } else if (t < 2 * EDG) {
        int e = t - EDG;
        int d = __ldg(d1 + e);
        int b = NBIN + d;
        int pos = g_off[b] + atomicAdd(&g_rank[b], 1);
        g_rec[EDG + pos]  = make_int2(__ldg(s1 + e), __float_as_int(__ldg(x1 + e)));
        g_sdst[EDG + pos] = d;
    }
}

// ---------------------------------------------------------------------------
// Edge kernel: mma.sync bf16 3-term split (fragment math verified R5-R7)
// over dst-SORTED edges; epilogue aggregates per-dst runs in registers and
// emits one red.v2 per run (~10-30x fewer atomics).
//   per-warp buffer: A-tile (stride 192B) aliased with D-tile (stride 272B)
// Blocks [0,EB) = a2s, [EB,2EB) = s2s.  EDG % 256 == 0.
// ---------------------------------------------------------------------------
#define AROWB 192
#define DSTR  272
#define WBUF  8704    // 32*272

__global__ void __launch_bounds__(128, 4) edge_mma_kernel(
    int eb,
    const float* __restrict__ W10, const float* __restrict__ W20,
    const float* __restrict__ b20,
    const float* __restrict__ W11, const float* __restrict__ W21,
    const float* __restrict__ b21)
{
    __shared__ __align__(16) char sAD[4][WBUF];          // 34816 B
    __shared__ __align__(16) uint32_t sBF[2][8][32][4];  // 8192 B
    __shared__ __align__(16) float sb2[64];              // 256 B

    int tid  = threadIdx.x;
    int wid  = tid >> 5;
    int lane = tid & 31;

    bool second = (blockIdx.x >= (unsigned)eb);
    int blk = second ? ((int)blockIdx.x - eb) : (int)blockIdx.x;

    const float* W1 = second ? W11 : W10;
    const float* W2 = second ? W21 : W20;
    const float* b2 = second ? b21 : b20;
    const float* __restrict__ Asrc = second ? g_Cpre : g_Apre;
    const float* __restrict__ Bdst = second ? g_Dpre : g_Bpre;
    float* __restrict__ sumbuf     = second ? g_sum_h : g_sum_u;
    size_t gbase = second ? (size_t)EDG : 0;

    // ---- bias copy + B-fragment table (once per CTA) ----
    if (tid < 64) sb2[tid] = __ldg(b2 + tid);
#pragma unroll
    for (int f = tid; f < 2048; f += 128) {
        int w      = f & 3;
        int lane_i = (f >> 2) & 31;
        int g      = (f >> 7) & 7;
        int half   = f >> 10;
        int nt_l   = g >> 1;
        int kt     = g & 1;
        int n  = (half * 4 + nt_l) * 8 + (lane_i >> 2);
        int k0 = kt * 16 + 2 * (lane_i & 3) + (w & 1) * 8;
        float w0 = __ldg(W2 + (k0 + 0) * 64 + n);
        float w1 = __ldg(W2 + (k0 + 1) * 64 + n);
        __nv_bfloat16 h0 = __float2bfloat16(w0);
        __nv_bfloat16 h1 = __float2bfloat16(w1);
        uint32_t val;
        if ((w >> 1) == 0) {
            val = pack_bf16x2(h0, h1);
        } else {
            val = pack_bf16x2(__float2bfloat16(w0 - __bfloat162float(h0)),
                              __float2bfloat16(w1 - __bfloat162float(h1)));
        }
        sBF[half][g][lane_i][w] = val;
    }
    __syncthreads();

    char* wt = sAD[wid];
    uint32_t tile_base = smem_u32(wt);

    int eslot = lane >> 3;
    int echunk = lane & 7;
    float4 w1d4 = __ldg(reinterpret_cast<const float4*>(W1 + 4 * 32) + echunk);

    uint32_t lrow   = ((lane >> 3) & 1) * 8 + (lane & 7);
    uint32_t lchunk = (lane >> 4) * 16;

    int gwarp = blk * 4 + wid;

#pragma unroll 1
    for (int tile = 0; tile < 2; ++tile) {
        int ebase = gwarp * 64 + tile * 32;
        int2 rd = __ldg(g_rec + gbase + ebase + lane);
        int d   = __ldg(g_sdst + gbase + ebase + lane);
        int s   = rd.x;
        float dv = __int_as_float(rd.y);

        // ---- stage hid tile (hi/lo bf16), 8 iterations x 4 edges ----
#pragma unroll 2
        for (int t = 0; t < 8; ++t) {
            int e = t * 4 + eslot;
            int ss   = __shfl_sync(0xffffffffu, s, e);
            int dd   = __shfl_sync(0xffffffffu, d, e);
            float dw = __shfl_sync(0xffffffffu, dv, e);
            float4 av = __ldg(reinterpret_cast<const float4*>(Asrc + ss * 32) + echunk);
            float4 bv = __ldg(reinterpret_cast<const float4*>(Bdst + dd * 32) + echunk);
            float h0 = leaky(av.x + bv.x + dw * w1d4.x);
            float h1 = leaky(av.y + bv.y + dw * w1d4.y);
            float h2 = leaky(av.z + bv.z + dw * w1d4.z);
            float h3 = leaky(av.w + bv.w + dw * w1d4.w);
            uint32_t hi01 = cvt_bf16x2(h0, h1);
            uint32_t hi23 = cvt_bf16x2(h2, h3);
            float l0 = h0 - __uint_as_float(hi01 << 16);
            float l1 = h1 - __uint_as_float(hi01 & 0xffff0000u);
            float l2 = h2 - __uint_as_float(hi23 << 16);
            float l3 = h3 - __uint_as_float(hi23 & 0xffff0000u);
            uint32_t lo01 = cvt_bf16x2(l0, l1);
            uint32_t lo23 = cvt_bf16x2(l2, l3);
            char* rowp = wt + e * AROWB + echunk * 8;
            *reinterpret_cast<uint2*>(rowp)      = make_uint2(hi01, hi23);
            *reinterpret_cast<uint2*>(rowp + 64) = make_uint2(lo01, lo23);
        }
        __syncwarp();

        // ---- all A fragments up front (A-tile consumed before D overwrite) ----
        uint32_t ah[2][2][4], al[2][2][4];
#pragma unroll
        for (int mt = 0; mt < 2; ++mt) {
            uint32_t rbase = tile_base + (mt * 16 + lrow) * AROWB + lchunk;
            ldsm_x4(rbase + 0,  ah[mt][0][0], ah[mt][0][1], ah[mt][0][2], ah[mt][0][3]);
            ldsm_x4(rbase + 32, ah[mt][1][0], ah[mt][1][1], ah[mt][1][2], ah[mt][1][3]);
            ldsm_x4(rbase + 64, al[mt][0][0], al[mt][0][1], al[mt][0][2], al[mt][0][3]);
            ldsm_x4(rbase + 96, al[mt][1][0], al[mt][1][1], al[mt][1][2], al[mt][1][3]);
        }
        __syncwarp();

        // ---- MMA + store raw D tile to smem (stride DSTR) ----
#pragma unroll
        for (int half = 0; half < 2; ++half) {
            uint32_t Bh[4][2][2], Bl[4][2][2];
#pragma unroll
            for (int g = 0; g < 8; ++g) {
                uint4 v = *reinterpret_cast<const uint4*>(&sBF[half][g][lane][0]);
                int nt = g >> 1, kt = g & 1;
                Bh[nt][kt][0] = v.x;
                Bh[nt][kt][1] = v.y;
                Bl[nt][kt][0] = v.z;
                Bl[nt][kt][1] = v.w;
            }
#pragma unroll
            for (int mt = 0; mt < 2; ++mt) {
                float C[4][4];
#pragma unroll
                for (int nt = 0; nt < 4; ++nt) {
                    float2 bb = *reinterpret_cast<const float2*>(
                        &sb2[(half * 4 + nt) * 8 + 2 * (lane & 3)]);
                    C[nt][0] = bb.x; C[nt][1] = bb.y;
                    C[nt][2] = bb.x; C[nt][3] = bb.y;
                }
#pragma unroll
                for (int nt = 0; nt < 4; ++nt) {
#pragma unroll
                    for (int kt = 0; kt < 2; ++kt) {
                        mma_bf16(C[nt][0], C[nt][1], C[nt][2], C[nt][3],
                                 ah[mt][kt][0], ah[mt][kt][1], ah[mt][kt][2], ah[mt][kt][3],
                                 Bh[nt][kt][0], Bh[nt][kt][1]);
                        mma_bf16(C[nt][0], C[nt][1], C[nt][2], C[nt][3],
                                 ah[mt][kt][0], ah[mt][kt][1], ah[mt][kt][2], ah[mt][kt][3],
                                 Bl[nt][kt][0], Bl[nt][kt][1]);
                        mma_bf16(C[nt][0], C[nt][1], C[nt][2], C[nt][3],
                                 al[mt][kt][0], al[mt][kt][1], al[mt][kt][2], al[mt][kt][3],
                                 Bh[nt][kt][0], Bh[nt][kt][1]);
                    }
                }
                char* drow = wt + (mt * 16 + (lane >> 2)) * DSTR
                           + half * 128 + 8 * (lane & 3);
#pragma unroll
                for (int nt = 0; nt < 4; ++nt) {
                    *reinterpret_cast<float2*>(drow + nt * 32) =
                        make_float2(C[nt][0], C[nt][1]);
                    *reinterpret_cast<float2*>(drow + 8 * DSTR + nt * 32) =
                        make_float2(C[nt][2], C[nt][3]);
                }
            }
        }
        __syncwarp();

        // ---- run-aggregated scatter: lane owns cols {2*lane, 2*lane+1} ----
        {
            float a0 = 0.f, a1 = 0.f;
            int prev = __shfl_sync(0xffffffffu, d, 0);
            const char* dcol = wt + lane * 8;
#pragma unroll 1
            for (int t = 0; t < 32; ++t) {
                int ddt = __shfl_sync(0xffffffffu, d, t);
                if (ddt != prev) {
                    red_v2(sumbuf + (size_t)prev * 64 + 2 * lane, a0, a1);
                    a0 = 0.f; a1 = 0.f; prev = ddt;
                }
                float2 v = *reinterpret_cast<const float2*>(dcol + t * DSTR);
                a0 += tanh_fast(v.x);
                a1 += tanh_fast(v.y);
            }
            red_v2(sumbuf + (size_t)prev * 64 + 2 * lane, a0, a1);
        }
        __syncwarp();
    }
}

// ---------------------------------------------------------------------------
// Node update (unchanged)
// ---------------------------------------------------------------------------
__global__ void __launch_bounds__(256) upd_kernel(
    const float* __restrict__ pos_s,
    const float* __restrict__ h,
    const float* __restrict__ W1,
    const float* __restrict__ b1,
    const float* __restrict__ W2,
    const float* __restrict__ b2,
    float* __restrict__ out)
{
    int lane = threadIdx.x & 31;
    int node = (blockIdx.x * blockDim.x + threadIdx.x) >> 5;
    if (node >= NS) return;
    float p0 = __ldg(pos_s + 2 * node);
    float p1 = __ldg(pos_s + 2 * node + 1);
    float acc = __ldg(b1 + lane)
              + p0 * __ldg(W1 + 0 * 32 + lane)
              + p1 * __ldg(W1 + 1 * 32 + lane);

    const float4* h4  = reinterpret_cast<const float4*>(h) + node * 16;
    const float4* su4 = reinterpret_cast<const float4*>(g_sum_u) + node * 16;
    const float4* sh4 = reinterpret_cast<const float4*>(g_sum_h) + node * 16;
#pragma unroll
    for (int q = 0; q < 16; ++q) {
        float4 v = __ldg(h4 + q);
        acc = fmaf(v.x, __ldg(W1 + (2 + 4 * q + 0) * 32 + lane), acc);
        acc = fmaf(v.y, __ldg(W1 + (2 + 4 * q + 1) * 32 + lane), acc);
        acc = fmaf(v.z, __ldg(W1 + (2 + 4 * q + 2) * 32 + lane), acc);
        acc = fmaf(v.w, __ldg(W1 + (2 + 4 * q + 3) * 32 + lane), acc);
    }
#pragma unroll
    for (int q = 0; q < 16; ++q) {
        float4 v = su4[q];
        acc = fmaf(v.x, __ldg(W1 + (66 + 4 * q + 0) * 32 + lane), acc);
        acc = fmaf(v.y, __ldg(W1 + (66 + 4 * q + 1) * 32 + lane), acc);
        acc = fmaf(v.z, __ldg(W1 + (66 + 4 * q + 2) * 32 + lane), acc);
        acc = fmaf(v.w, __ldg(W1 + (66 + 4 * q + 3) * 32 + lane), acc);
    }
#pragma unroll
    for (int q = 0; q < 16; ++q) {
        float4 v = sh4[q];
        acc = fmaf(v.x, __ldg(W1 + (130 + 4 * q + 0) * 32 + lane), acc);
        acc = fmaf(v.y, __ldg(W1 + (130 + 4 * q + 1) * 32 + lane), acc);
        acc = fmaf(v.z, __ldg(W1 + (130 + 4 * q + 2) * 32 + lane), acc);
        acc = fmaf(v.w, __ldg(W1 + (130 + 4 * q + 3) * 32 + lane), acc);
    }
    acc = leaky(acc);

    float m0 = __ldg(b2 + 2 * lane);
    float m1 = __ldg(b2 + 2 * lane + 1);
#pragma unroll
    for (int k = 0; k < 32; ++k) {
        float hv = __shfl_sync(0xffffffffu, acc, k);
        float2 wv = __ldg(reinterpret_cast<const float2*>(W2 + k * 64) + lane);
        m0 = fmaf(hv, wv.x, m0);
        m1 = fmaf(hv, wv.y, m1);
    }
    float2 o;
    o.x = tanhf(m0);
    o.y = tanhf(m1);
    reinterpret_cast<float2*>(out)[node * 32 + lane] = o;
}

// ---------------------------------------------------------------------------
extern "C" void kernel_launch(void* const* d_in, const int* in_sizes, int n_in,
                              void* d_out, int out_size)
{
    const float* h        = (const float*)d_in[0];
    const float* u        = (const float*)d_in[1];
    const float* pos_s    = (const float*)d_in[2];
    const float* pos_a    = (const float*)d_in[3];
    const float* dis_a2s  = (const float*)d_in[4];
    const float* dis_s2s  = (const float*)d_in[5];
    const int*   a2s_src  = (const int*)d_in[6];
    const int*   a2s_dst  = (const int*)d_in[7];
    const int*   s2s_src  = (const int*)d_in[8];
    const int*   s2s_dst  = (const int*)d_in[9];
    const float* a2s_W1   = (const float*)d_in[10];
    const float* a2s_b1   = (const float*)d_in[11];
    const float* a2s_W2   = (const float*)d_in[12];
    const float* a2s_b2   = (const float*)d_in[13];
    const float* s2s_W1   = (const float*)d_in[14];
    const float* s2s_b1   = (const float*)d_in[15];
    const float* s2s_W2   = (const float*)d_in[16];
    const float* s2s_b2   = (const float*)d_in[17];
    const float* upd_W1   = (const float*)d_in[18];
    const float* upd_b1   = (const float*)d_in[19];
    const float* upd_W2   = (const float*)d_in[20];
    const float* upd_b2   = (const float*)d_in[21];
    float* out = (float*)d_out;

    const int WPB = 8;

    // Node-side precompute (also zeroes sum buffers)
    int pre_tasks = NS + NA + NS;
    pre_kernel<<<(pre_tasks + WPB - 1) / WPB, 256>>>(
        pos_s, pos_a, u, h, a2s_W1, a2s_b1, s2s_W1, s2s_b1);

    // Counting sort of both edge lists by dst
    sort_zero<<<SCAN_BLOCKS, 256>>>();
    sort_hist<<<(2 * EDG) / 256, 256>>>(a2s_dst, s2s_dst);
    scan_blocks<<<SCAN_BLOCKS, 256>>>();
    scan_tops<<<1, 512>>>();
    scan_apply<<<SCAN_BLOCKS, 256>>>();
    sort_place<<<(2 * EDG) / 256, 256>>>(a2s_src, a2s_dst, dis_a2s,
                                         s2s_src, s2s_dst, dis_s2s);

    // Edge passes on tensor cores over sorted edges
    int eb = EDG / 256;                   // 6250 per pass
    edge_mma_kernel<<<2 * eb, 128>>>(
        eb, a2s_W1, a2s_W2, a2s_b2, s2s_W1, s2s_W2, s2s_b2);

    // Node update
    upd_kernel<<<(NS + WPB - 1) / WPB, 256>>>(pos_s, h, upd_W1, upd_b1, upd_W2, upd_b2, out);
}